// round 10
// baseline (speedup 1.0000x reference)
#include <cuda_runtime.h>
#include <cuda_fp16.h>
#include <math.h>
#include <stdint.h>

// Problem constants
#define N_B   4
#define T_S   2048
#define D_M   1024
#define H_N   16
#define DH    64
#define MROWS (N_B * T_S)   // 8192
#define GK    1024          // GEMM K

// ---------------------------------------------------------------------------
// Scratch (alloc-free rule: __device__ globals)
// ---------------------------------------------------------------------------
__device__ float g_Q  [(size_t)MROWS * D_M];
__device__ float g_K  [(size_t)MROWS * D_M];
__device__ float g_V  [(size_t)MROWS * D_M];
__device__ float g_ctx[(size_t)MROWS * D_M];

// ---------------------------------------------------------------------------
// Helpers (sm_100 plain target: NO tcgen05)
// ---------------------------------------------------------------------------
__device__ __forceinline__ uint32_t smem_to_u32(const void* p) {
    uint32_t a;
    asm("{ .reg .u64 t; cvta.to.shared.u64 t, %1; cvt.u32.u64 %0, t; }"
        : "=r"(a) : "l"(p));
    return a;
}
__device__ __forceinline__ uint32_t packh2(float lo, float hi) {
    __half2 h = __floats2half2_rn(lo, hi);
    return *(uint32_t*)&h;
}
// D(16x8,f32) += A(16x16,f16 row) * B(16x8,f16 col)
__device__ __forceinline__ void mma_f16(float* d, const uint32_t* a,
                                        uint32_t b0, uint32_t b1) {
    asm volatile(
        "mma.sync.aligned.m16n8k16.row.col.f32.f16.f16.f32 "
        "{%0,%1,%2,%3}, {%4,%5,%6,%7}, {%8,%9}, {%0,%1,%2,%3};"
        : "+f"(d[0]), "+f"(d[1]), "+f"(d[2]), "+f"(d[3])
        : "r"(a[0]), "r"(a[1]), "r"(a[2]), "r"(a[3]),
          "r"(b0), "r"(b1));
}
__device__ __forceinline__ void ldsm_x2(uint32_t addr, uint32_t& r0, uint32_t& r1) {
    asm volatile("ldmatrix.sync.aligned.m8n8.x2.shared.b16 {%0,%1}, [%2];"
                 : "=r"(r0), "=r"(r1) : "r"(addr));
}
__device__ __forceinline__ void ldsm_x2t(uint32_t addr, uint32_t& r0, uint32_t& r1) {
    asm volatile("ldmatrix.sync.aligned.m8n8.x2.trans.shared.b16 {%0,%1}, [%2];"
                 : "=r"(r0), "=r"(r1) : "r"(addr));
}
__device__ __forceinline__ void ldsm_x4(uint32_t addr, uint32_t* r) {
    asm volatile("ldmatrix.sync.aligned.m8n8.x4.shared.b16 {%0,%1,%2,%3}, [%4];"
                 : "=r"(r[0]), "=r"(r[1]), "=r"(r[2]), "=r"(r[3]) : "r"(addr));
}

// ---------------------------------------------------------------------------
// FP16 tensor-core GEMM: C[m][n] = sum_k A[m][k]*B[n][k] + bias[n]
// 128x128x32 CTA tile, 8 warps (2M x 4N), warp 64x32, m16n8k16.
// Smem tiles f16, row stride 40 halves (80 B) => conflict-free ldmatrix.
// Loader: gmem fp32 -> regs -> packh2 -> STS f16, double buffered.
// Fragment patterns identical to the flash kernel (validated R9):
//   A = ldsm_x4 ("poff" pattern), B = ldsm_x2 ("koff" pattern).
// ---------------------------------------------------------------------------
#define GSTR   40                       // halves per smem row
#define GTILEB (128 * GSTR * 2)         // 10240 B per tile
#define GEMM_SMEM_BYTES (4 * GTILEB)    // A0 A1 B0 B1 = 40960 B

__global__ __launch_bounds__(256, 2)
void hgemm_f16(const float* __restrict__ A, const float* __restrict__ B,
               const float* __restrict__ bias, float* __restrict__ C)
{
    extern __shared__ char smc[];
    const uint32_t sb = smem_to_u32(smc);
    const int tid  = threadIdx.x;
    const int wid  = tid >> 5;
    const int lane = tid & 31;
    const int g    = lane >> 2;
    const int tg   = lane & 3;
    const int warp_m = wid & 1;
    const int warp_n = wid >> 1;
    const int m0 = blockIdx.y * 128;
    const int n0 = blockIdx.x * 128;

    // loader mapping: row = tid&127, 16-col half = tid>>7
    const int lr = tid & 127;
    const int lh = tid >> 7;
    const float* Ag = A + (size_t)(m0 + lr) * GK + lh * 16;
    const float* Bg = B + (size_t)(n0 + lr) * GK + lh * 16;
    const uint32_t sdst = (uint32_t)(lr * (GSTR * 2) + lh * 32);  // bytes

    // ldmatrix per-lane offsets (bytes)
    const uint32_t aoff = (uint32_t)(((lane & 15) * GSTR + (lane >> 4) * 8) * 2);
    const uint32_t boff = (uint32_t)(((lane & 7) * GSTR + ((lane >> 3) & 1) * 8) * 2);

    float4 ast[4], bst[4];
    // prologue: k-tile 0 -> buf 0
    #pragma unroll
    for (int j = 0; j < 4; ++j) { ast[j] = *(const float4*)(Ag + j * 4);
                                  bst[j] = *(const float4*)(Bg + j * 4); }
    {
        char* ad = smc + sdst;
        char* bd = smc + 2 * GTILEB + sdst;
        #pragma unroll
        for (int j = 0; j < 4; ++j) {
            *(uint2*)(ad + j * 8) = make_uint2(packh2(ast[j].x, ast[j].y),
                                               packh2(ast[j].z, ast[j].w));
            *(uint2*)(bd + j * 8) = make_uint2(packh2(bst[j].x, bst[j].y),
                                               packh2(bst[j].z, bst[j].w));
        }
    }

    float acc[4][4][4];
    #pragma unroll
    for (int mt = 0; mt < 4; ++mt)
        #pragma unroll
        for (int nt = 0; nt < 4; ++nt)
            #pragma unroll
            for (int u = 0; u < 4; ++u) acc[mt][nt][u] = 0.0f;

    const int NT = GK / 32;   // 32 k-tiles
    for (int kt = 0; kt < NT; ++kt) {
        const int buf = kt & 1;
        const int nxt = (kt + 1 < NT);
        const int ko = (kt + 1) * 32;

        if (nxt) {   // stage next A early (L2 latency hidden by compute)
            #pragma unroll
            for (int j = 0; j < 4; ++j) ast[j] = *(const float4*)(Ag + ko + j * 4);
        }
        __syncthreads();   // buf's STS visible; buf^1 reads (iter kt-1) done

        const uint32_t AB = sb + buf * GTILEB;
        const uint32_t BB = sb + 2 * GTILEB + buf * GTILEB;

        // ---- k16 step 0 ----
        {
            uint32_t af[4][4], bf[4][2];
            #pragma unroll
            for (int mt = 0; mt < 4; ++mt)
                ldsm_x4(AB + (uint32_t)((warp_m * 64 + mt * 16) * GSTR * 2) + aoff,
                        af[mt]);
            #pragma unroll
            for (int nt = 0; nt < 4; ++nt)
                ldsm_x2(BB + (uint32_t)((warp_n * 32 + nt * 8) * GSTR * 2) + boff,
                        bf[nt][0], bf[nt][1]);
            #pragma unroll
            for (int mt = 0; mt < 4; ++mt)
                #pragma unroll
                for (int nt = 0; nt < 4; ++nt)
                    mma_f16(acc[mt][nt], af[mt], bf[nt][0], bf[nt][1]);
        }

        if (nxt) {   // stage next B mid-compute
            #pragma unroll
            for (int j = 0; j < 4; ++j) bst[j] = *(const float4*)(Bg + ko + j * 4);
        }

        // ---- k16 step 1 ----
        {
            uint32_t af[4][4], bf[4][2];
            #pragma unroll
            for (int mt = 0; mt < 4; ++mt)
                ldsm_x4(AB + (uint32_t)((warp_m * 64 + mt * 16) * GSTR * 2 + 32) + aoff,
                        af[mt]);
            #pragma unroll
            for (int nt = 0; nt < 4; ++nt)
                ldsm_x2(BB + (uint32_t)((warp_n * 32 + nt * 8) * GSTR * 2 + 32) + boff,
                        bf[nt][0], bf[nt][1]);
            #pragma unroll
            for (int mt = 0; mt < 4; ++mt)
                #pragma unroll
                for (int nt = 0; nt < 4; ++nt)
                    mma_f16(acc[mt][nt], af[mt], bf[nt][0], bf[nt][1]);
        }

        if (nxt) {   // convert + store next tiles into buf^1 (consumed already)
            char* ad = smc + (buf ^ 1) * GTILEB + sdst;
            char* bd = smc + (2 + (buf ^ 1)) * GTILEB + sdst;
            #pragma unroll
            for (int j = 0; j < 4; ++j) {
                *(uint2*)(ad + j * 8) = make_uint2(packh2(ast[j].x, ast[j].y),
                                                   packh2(ast[j].z, ast[j].w));
                *(uint2*)(bd + j * 8) = make_uint2(packh2(bst[j].x, bst[j].y),
                                                   packh2(bst[j].z, bst[j].w));
            }
        }
    }

    // epilogue: add bias, write C (c0/c1 row g, c2/c3 row g+8)
    #pragma unroll
    for (int nt = 0; nt < 4; ++nt) {
        const int col = n0 + warp_n * 32 + nt * 8 + tg * 2;
        const float b0 = bias[col], b1 = bias[col + 1];
        #pragma unroll
        for (int mt = 0; mt < 4; ++mt) {
            const int row = m0 + warp_m * 64 + mt * 16 + g;
            float2 v0 = make_float2(acc[mt][nt][0] + b0, acc[mt][nt][1] + b1);
            float2 v1 = make_float2(acc[mt][nt][2] + b0, acc[mt][nt][3] + b1);
            *(float2*)(C + (size_t)row * D_M + col)       = v0;
            *(float2*)(C + (size_t)(row + 8) * D_M + col) = v1;
        }
    }
}

// ---------------------------------------------------------------------------
// Flash attention — fp16 (unchanged from R9-passing version).
// ---------------------------------------------------------------------------
#define SK    64                      // keys per s-tile
#define KSTRH 72                      // halves per K/V smem row (144 B)
#define KVTB  (SK * KSTRH * 2)        // 9216 B per tile
#define OFF_VH (2 * KVTB)
#define OFF_PH (4 * KVTB)
#define FA_SMEM_BYTES (4 * KVTB + 128 * KSTRH * 2)  // 55296

__global__ __launch_bounds__(256, 2)
void flash_attn_f16(const float* __restrict__ Q, const float* __restrict__ K,
                    const float* __restrict__ V, const int* __restrict__ mask,
                    float* __restrict__ ctx)
{
    extern __shared__ char smc[];
    const uint32_t sb = smem_to_u32(smc);

    const int tid  = threadIdx.x;
    const int wid  = tid >> 5;
    const int lane = tid & 31;
    const int g    = lane >> 2;
    const int tg   = lane & 3;
    const int t0 = blockIdx.x * 128;
    const int h  = blockIdx.y;
    const int n  = blockIdx.z;

    const size_t qrow = (size_t)(n * T_S + t0 + wid * 16 + g);
    const float* Qp0 = Q + qrow * D_M + h * DH;
    const float* Qp1 = Qp0 + (size_t)8 * D_M;
    uint32_t qf[4][4];
    #pragma unroll
    for (int ks = 0; ks < 4; ++ks) {
        const int c = ks * 16 + 2 * tg;
        qf[ks][0] = packh2(Qp0[c],     Qp0[c + 1]);
        qf[ks][1] = packh2(Qp1[c],     Qp1[c + 1]);
        qf[ks][2] = packh2(Qp0[c + 8], Qp0[c + 9]);
        qf[ks][3] = packh2(Qp1[c + 8], Qp1[c + 9]);
    }

    const float rsc0 = (mask[n * T_S + t0 + wid * 16 + g]     != 0) ? 0.125f : 0.0f;
    const float rsc1 = (mask[n * T_S + t0 + wid * 16 + g + 8] != 0) ? 0.125f : 0.0f;

    float m0 = -1e30f, l0 = 0.0f, m1 = -1e30f, l1 = 0.0f;
    float oacc[8][4];
    #pragma unroll
    for (int nt = 0; nt < 8; ++nt)
        #pragma unroll
        for (int u = 0; u < 4; ++u) oacc[nt][u] = 0.0f;

    const int cr = tid >> 2;
    const int cq = (tid & 3) * 16;
    const float* Kg = K + ((size_t)(n * T_S) + cr) * D_M + h * DH + cq;
    const float* Vg = V + ((size_t)(n * T_S) + cr) * D_M + h * DH + cq;
    const uint32_t cdst = (uint32_t)(cr * (KSTRH * 2) + cq * 2);

    const uint32_t koff = (uint32_t)(((lane & 7) * KSTRH + ((lane >> 3) & 1) * 8) * 2);
    const uint32_t voff = (uint32_t)((lane & 15) * KSTRH * 2);
    const uint32_t poff = (uint32_t)((lane & 15) * KSTRH * 2 + ((lane >> 4) & 1) * 16);
    const uint32_t PhB  = sb + OFF_PH + wid * 16 * (KSTRH * 2);

    float4 kst[4], vst[4];
    #pragma unroll
    for (int j = 0; j < 4; ++j) { kst[j] = *(const float4*)(Kg + j * 4);
                                  vst[j] = *(const float4*)(Vg + j * 4); }
    {
        char* kd = smc + cdst;
        char* vd = smc + OFF_VH + cdst;
        #pragma unroll
        for (int j = 0; j < 4; ++j) {
            *(uint2*)(kd + j * 8) = make_uint2(packh2(kst[j].x, kst[j].y),
                                               packh2(kst[j].z, kst[j].w));
            *(uint2*)(vd + j * 8) = make_uint2(packh2(vst[j].x, vst[j].y),
                                               packh2(vst[j].z, vst[j].w));
        }
    }

    const int NST = T_S / SK;   // 32
    for (int st = 0; st < NST; ++st) {
        const int buf = st & 1;
        const int nxt = (st + 1 < NST);
        const size_t go = (size_t)(st + 1) * SK * D_M;

        if (nxt) {
            #pragma unroll
            for (int j = 0; j < 4; ++j) kst[j] = *(const float4*)(Kg + go + j * 4);
        }
        __syncthreads();

        const uint32_t KhB = sb + buf * KVTB;
        const uint32_t VhB = sb + OFF_VH + buf * KVTB;

        float sacc[8][4];
        #pragma unroll
        for (int nt = 0; nt < 8; ++nt)
            #pragma unroll
            for (int u = 0; u < 4; ++u) sacc[nt][u] = 0.0f;

        #pragma unroll
        for (int ks = 0; ks < 4; ++ks) {
            #pragma unroll
            for (int nt = 0; nt < 8; ++nt) {
                uint32_t b0, b1;
                ldsm_x2(KhB + (uint32_t)((nt * 8 * KSTRH + ks * 16) * 2) + koff, b0, b1);
                mma_f16(sacc[nt], qf[ks], b0, b1);
            }
        }

        if (nxt) {
            #pragma unroll
            for (int j = 0; j < 4; ++j) vst[j] = *(const float4*)(Vg + go + j * 4);
        }

        {
            float mx0 = -1e30f, mx1 = -1e30f;
            #pragma unroll
            for (int nt = 0; nt < 8; ++nt) {
                sacc[nt][0] *= rsc0; sacc[nt][1] *= rsc0;
                sacc[nt][2] *= rsc1; sacc[nt][3] *= rsc1;
                mx0 = fmaxf(mx0, fmaxf(sacc[nt][0], sacc[nt][1]));
                mx1 = fmaxf(mx1, fmaxf(sacc[nt][2], sacc[nt][3]));
            }
            mx0 = fmaxf(mx0, __shfl_xor_sync(0xffffffffu, mx0, 1));
            mx0 = fmaxf(mx0, __shfl_xor_sync(0xffffffffu, mx0, 2));
            mx1 = fmaxf(mx1, __shfl_xor_sync(0xffffffffu, mx1, 1));
            mx1 = fmaxf(mx1, __shfl_xor_sync(0xffffffffu, mx1, 2));

            const float mn0 = fmaxf(m0, mx0), mn1 = fmaxf(m1, mx1);
            const float cf0 = __expf(m0 - mn0), cf1 = __expf(m1 - mn1);
            float rs0 = 0.0f, rs1 = 0.0f;

            char* Pr0 = smc + OFF_PH + (wid * 16 + g)     * (KSTRH * 2) + tg * 4;
            char* Pr1 = smc + OFF_PH + (wid * 16 + g + 8) * (KSTRH * 2) + tg * 4;
            #pragma unroll
            for (int nt = 0; nt < 8; ++nt) {
                float p0 = __expf(sacc[nt][0] - mn0);
                float p1 = __expf(sacc[nt][1] - mn0);
                float p2 = __expf(sacc[nt][2] - mn1);
                float p3 = __expf(sacc[nt][3] - mn1);
                rs0 += p0 + p1;
                rs1 += p2 + p3;
                *(uint32_t*)(Pr0 + nt * 16) = packh2(p0, p1);
                *(uint32_t*)(Pr1 + nt * 16) = packh2(p2, p3);
            }
            rs0 += __shfl_xor_sync(0xffffffffu, rs0, 1);
            rs0 += __shfl_xor_sync(0xffffffffu, rs0, 2);
            rs1 += __shfl_xor_sync(0xffffffffu, rs1, 1);
            rs1 += __shfl_xor_sync(0xffffffffu, rs1, 2);

            m0 = mn0; l0 = l0 * cf0 + rs0;
            m1 = mn1; l1 = l1 * cf1 + rs1;
            #pragma unroll
            for (int nt = 0; nt < 8; ++nt) {
                oacc[nt][0] *= cf0; oacc[nt][1] *= cf0;
                oacc[nt][2] *= cf1; oacc[nt][3] *= cf1;
            }
        }
        __syncwarp();

        if (nxt) {
            char* kd = smc + (buf ^ 1) * KVTB + cdst;
            #pragma unroll
            for (int j = 0; j < 4; ++j)
                *(uint2*)(kd + j * 8) = make_uint2(packh2(kst[j].x, kst[j].y),
                                                   packh2(kst[j].z, kst[j].w));
        }

        #pragma unroll
        for (int ks = 0; ks < 4; ++ks) {
            uint32_t af[4];
            ldsm_x4(PhB + ks * 32 + poff, af);
            #pragma unroll
            for (int nt = 0; nt < 8; ++nt) {
                uint32_t b0, b1;
                ldsm_x2t(VhB + (uint32_t)((ks * 16 * KSTRH + nt * 8) * 2) + voff, b0, b1);
                mma_f16(oacc[nt], af, b0, b1);
            }
        }

        if (nxt) {
            char* vd = smc + OFF_VH + (buf ^ 1) * KVTB + cdst;
            #pragma unroll
            for (int j = 0; j < 4; ++j)
                *(uint2*)(vd + j * 8) = make_uint2(packh2(vst[j].x, vst[j].y),
                                                   packh2(vst[j].z, vst[j].w));
        }
    }

    const float inv0 = 1.0f / l0, inv1 = 1.0f / l1;
    float* op0 = ctx + qrow * D_M + h * DH;
    float* op1 = op0 + (size_t)8 * D_M;
    #pragma unroll
    for (int nt = 0; nt < 8; ++nt) {
        const int col = nt * 8 + tg * 2;
        *(float2*)(op0 + col) = make_float2(oacc[nt][0] * inv0, oacc[nt][1] * inv0);
        *(float2*)(op1 + col) = make_float2(oacc[nt][2] * inv1, oacc[nt][3] * inv1);
    }
}

// ---------------------------------------------------------------------------
// Launch
// ---------------------------------------------------------------------------
extern "C" void kernel_launch(void* const* d_in, const int* in_sizes, int n_in,
                              void* d_out, int out_size)
{
    (void)in_sizes; (void)n_in; (void)out_size;

    const float* query = (const float*)d_in[0];
    const int*   mask  = (const int*)  d_in[1];
    const float* Wq    = (const float*)d_in[2];
    const float* bq    = (const float*)d_in[3];
    const float* Wk    = (const float*)d_in[4];
    const float* bk    = (const float*)d_in[5];
    const float* Wv    = (const float*)d_in[6];
    const float* bv    = (const float*)d_in[7];
    const float* Wo    = (const float*)d_in[8];
    const float* bo    = (const float*)d_in[9];
    float* out = (float*)d_out;

    float *Qd, *Kd, *Vd, *Cd;
    cudaGetSymbolAddress((void**)&Qd, g_Q);
    cudaGetSymbolAddress((void**)&Kd, g_K);
    cudaGetSymbolAddress((void**)&Vd, g_V);
    cudaGetSymbolAddress((void**)&Cd, g_ctx);

    cudaFuncSetAttribute(hgemm_f16,
                         cudaFuncAttributeMaxDynamicSharedMemorySize,
                         GEMM_SMEM_BYTES);
    cudaFuncSetAttribute(flash_attn_f16,
                         cudaFuncAttributeMaxDynamicSharedMemorySize,
                         FA_SMEM_BYTES);

    dim3 gemm_grid(D_M / 128, MROWS / 128);  // (8, 64)

    hgemm_f16<<<gemm_grid, 256, GEMM_SMEM_BYTES>>>(query, Wq, bq, Qd);
    hgemm_f16<<<gemm_grid, 256, GEMM_SMEM_BYTES>>>(query, Wk, bk, Kd);
    hgemm_f16<<<gemm_grid, 256, GEMM_SMEM_BYTES>>>(query, Wv, bv, Vd);

    flash_attn_f16<<<dim3(T_S / 128, H_N, N_B), 256, FA_SMEM_BYTES>>>(
        Qd, Kd, Vd, mask, Cd);

    hgemm_f16<<<gemm_grid, 256, GEMM_SMEM_BYTES>>>(Cd, Wo, bo, out);
}

// round 11
// speedup vs baseline: 1.8463x; 1.8463x over previous
#include <cuda_runtime.h>
#include <cuda_fp16.h>
#include <math.h>
#include <stdint.h>

// Problem constants
#define N_B   4
#define T_S   2048
#define D_M   1024
#define H_N   16
#define DH    64
#define MROWS (N_B * T_S)   // 8192
#define GK    1024          // GEMM K

// ---------------------------------------------------------------------------
// Scratch (alloc-free rule: __device__ globals) — all f16 now
// ---------------------------------------------------------------------------
__device__ __half g_qh  [(size_t)MROWS * D_M];   // query in f16
__device__ __half g_Qh  [(size_t)MROWS * D_M];
__device__ __half g_Kh  [(size_t)MROWS * D_M];
__device__ __half g_Vh  [(size_t)MROWS * D_M];
__device__ __half g_ctxh[(size_t)MROWS * D_M];
__device__ __half g_Wqh [(size_t)D_M * D_M];
__device__ __half g_Wkh [(size_t)D_M * D_M];
__device__ __half g_Wvh [(size_t)D_M * D_M];
__device__ __half g_Woh [(size_t)D_M * D_M];

// ---------------------------------------------------------------------------
// Helpers (sm_100 plain target: NO tcgen05)
// ---------------------------------------------------------------------------
__device__ __forceinline__ uint32_t smem_to_u32(const void* p) {
    uint32_t a;
    asm("{ .reg .u64 t; cvta.to.shared.u64 t, %1; cvt.u32.u64 %0, t; }"
        : "=r"(a) : "l"(p));
    return a;
}
__device__ __forceinline__ void cpa16(uint32_t dst, const void* src) {
    asm volatile("cp.async.cg.shared.global [%0], [%1], 16;"
                 :: "r"(dst), "l"(src) : "memory");
}
#define CP_COMMIT() asm volatile("cp.async.commit_group;" ::: "memory")

__device__ __forceinline__ uint32_t packh2(float lo, float hi) {
    __half2 h = __floats2half2_rn(lo, hi);
    return *(uint32_t*)&h;
}
// D(16x8,f32) += A(16x16,f16 row) * B(16x8,f16 col)
__device__ __forceinline__ void mma_f16(float* d, const uint32_t* a,
                                        uint32_t b0, uint32_t b1) {
    asm volatile(
        "mma.sync.aligned.m16n8k16.row.col.f32.f16.f16.f32 "
        "{%0,%1,%2,%3}, {%4,%5,%6,%7}, {%8,%9}, {%0,%1,%2,%3};"
        : "+f"(d[0]), "+f"(d[1]), "+f"(d[2]), "+f"(d[3])
        : "r"(a[0]), "r"(a[1]), "r"(a[2]), "r"(a[3]),
          "r"(b0), "r"(b1));
}
__device__ __forceinline__ void ldsm_x2(uint32_t addr, uint32_t& r0, uint32_t& r1) {
    asm volatile("ldmatrix.sync.aligned.m8n8.x2.shared.b16 {%0,%1}, [%2];"
                 : "=r"(r0), "=r"(r1) : "r"(addr));
}
__device__ __forceinline__ void ldsm_x2t(uint32_t addr, uint32_t& r0, uint32_t& r1) {
    asm volatile("ldmatrix.sync.aligned.m8n8.x2.trans.shared.b16 {%0,%1}, [%2];"
                 : "=r"(r0), "=r"(r1) : "r"(addr));
}
__device__ __forceinline__ void ldsm_x4(uint32_t addr, uint32_t* r) {
    asm volatile("ldmatrix.sync.aligned.m8n8.x4.shared.b16 {%0,%1,%2,%3}, [%4];"
                 : "=r"(r[0]), "=r"(r[1]), "=r"(r[2]), "=r"(r[3]) : "r"(addr));
}

// ---------------------------------------------------------------------------
// fp32 -> fp16 bulk convert (once per launch; ~15 us total)
// ---------------------------------------------------------------------------
__global__ void cvt_f32_f16(const float* __restrict__ in,
                            __half* __restrict__ out, int n)
{
    int i = (blockIdx.x * blockDim.x + threadIdx.x) * 8;
    if (i >= n) return;
    float4 a = *(const float4*)(in + i);
    float4 b = *(const float4*)(in + i + 4);
    uint4 o;
    o.x = packh2(a.x, a.y); o.y = packh2(a.z, a.w);
    o.z = packh2(b.x, b.y); o.w = packh2(b.z, b.w);
    *(uint4*)(out + i) = o;
}

// ---------------------------------------------------------------------------
// Pure FP16 tensor-core GEMM: C[m][n] = sum_k A[m][k]*B[n][k] + bias[n]
// A,B f16 row-major in gmem; cp.async double-buffered f16 smem (no staging
// regs, no in-kernel CVT); ldmatrix fragments; m16n8k16.
// 128x128x32 tile, 8 warps (2M x 4N). OutT = __half (QKV) or float (final).
// ---------------------------------------------------------------------------
#define GSTR   40                       // halves per smem row (80 B)
#define GTILEB (128 * GSTR * 2)         // 10240 B per tile
#define GEMM_SMEM_BYTES (4 * GTILEB)    // A0 A1 B0 B1 = 40960 B

template<typename OutT>
__global__ __launch_bounds__(256, 2)
void hgemm_f16(const __half* __restrict__ A, const __half* __restrict__ B,
               const float* __restrict__ bias, OutT* __restrict__ C)
{
    extern __shared__ char smc[];
    const uint32_t sb = smem_to_u32(smc);
    const int tid  = threadIdx.x;
    const int wid  = tid >> 5;
    const int lane = tid & 31;
    const int g    = lane >> 2;
    const int tg   = lane & 3;
    const int warp_m = wid & 1;
    const int warp_n = wid >> 1;
    const int m0 = blockIdx.y * 128;
    const int n0 = blockIdx.x * 128;

    // loader: 512 16B-chunks per operand per tile; thread -> 2 chunks (one row)
    const int lr = tid >> 1;             // row 0..127
    const int lc = (tid & 1) * 16;       // half-col 0 or 16
    const __half* Ag = A + (size_t)(m0 + lr) * GK + lc;
    const __half* Bg = B + (size_t)(n0 + lr) * GK + lc;
    const uint32_t sdst = (uint32_t)(lr * (GSTR * 2) + lc * 2);  // bytes

    // ldmatrix per-lane offsets (bytes) — validated R9/R10 patterns
    const uint32_t aoff = (uint32_t)(((lane & 15) * GSTR + (lane >> 4) * 8) * 2);
    const uint32_t boff = (uint32_t)(((lane & 7) * GSTR + ((lane >> 3) & 1) * 8) * 2);

    // prologue: k-tile 0 -> buf 0
    cpa16(sb + sdst,                Ag);
    cpa16(sb + sdst + 16,           Ag + 8);
    cpa16(sb + 2 * GTILEB + sdst,      Bg);
    cpa16(sb + 2 * GTILEB + sdst + 16, Bg + 8);
    CP_COMMIT();

    float acc[4][4][4];
    #pragma unroll
    for (int mt = 0; mt < 4; ++mt)
        #pragma unroll
        for (int nt = 0; nt < 4; ++nt)
            #pragma unroll
            for (int u = 0; u < 4; ++u) acc[mt][nt][u] = 0.0f;

    const int NT = GK / 32;   // 32 k-tiles
    for (int kt = 0; kt < NT; ++kt) {
        const int buf = kt & 1;
        if (kt + 1 < NT) {
            const int nb = buf ^ 1;
            const __half* Ag2 = Ag + (kt + 1) * 32;
            const __half* Bg2 = Bg + (kt + 1) * 32;
            cpa16(sb + nb * GTILEB + sdst,                Ag2);
            cpa16(sb + nb * GTILEB + sdst + 16,           Ag2 + 8);
            cpa16(sb + (2 + nb) * GTILEB + sdst,          Bg2);
            cpa16(sb + (2 + nb) * GTILEB + sdst + 16,     Bg2 + 8);
            CP_COMMIT();
            asm volatile("cp.async.wait_group 1;" ::: "memory");
        } else {
            asm volatile("cp.async.wait_group 0;" ::: "memory");
        }
        __syncthreads();

        const uint32_t AB = sb + buf * GTILEB;
        const uint32_t BB = sb + (2 + buf) * GTILEB;

        #pragma unroll
        for (int ks = 0; ks < 2; ++ks) {        // two k16 steps
            uint32_t af[4][4], bf[4][2];
            #pragma unroll
            for (int mt = 0; mt < 4; ++mt)
                ldsm_x4(AB + (uint32_t)((warp_m * 64 + mt * 16) * GSTR * 2 + ks * 32)
                           + aoff, af[mt]);
            #pragma unroll
            for (int nt = 0; nt < 4; ++nt)
                ldsm_x2(BB + (uint32_t)((warp_n * 32 + nt * 8) * GSTR * 2 + ks * 32)
                           + boff, bf[nt][0], bf[nt][1]);
            #pragma unroll
            for (int mt = 0; mt < 4; ++mt)
                #pragma unroll
                for (int nt = 0; nt < 4; ++nt)
                    mma_f16(acc[mt][nt], af[mt], bf[nt][0], bf[nt][1]);
        }
        __syncthreads();
    }

    // epilogue: add bias, write C
    #pragma unroll
    for (int nt = 0; nt < 4; ++nt) {
        const int col = n0 + warp_n * 32 + nt * 8 + tg * 2;
        const float b0 = bias[col], b1 = bias[col + 1];
        #pragma unroll
        for (int mt = 0; mt < 4; ++mt) {
            const int row = m0 + warp_m * 64 + mt * 16 + g;
            if (sizeof(OutT) == 2) {
                __half* Ch = (__half*)C;
                *(uint32_t*)(Ch + (size_t)row * D_M + col) =
                    packh2(acc[mt][nt][0] + b0, acc[mt][nt][1] + b1);
                *(uint32_t*)(Ch + (size_t)(row + 8) * D_M + col) =
                    packh2(acc[mt][nt][2] + b0, acc[mt][nt][3] + b1);
            } else {
                float* Cf = (float*)C;
                *(float2*)(Cf + (size_t)row * D_M + col) =
                    make_float2(acc[mt][nt][0] + b0, acc[mt][nt][1] + b1);
                *(float2*)(Cf + (size_t)(row + 8) * D_M + col) =
                    make_float2(acc[mt][nt][2] + b0, acc[mt][nt][3] + b1);
            }
        }
    }
}

// ---------------------------------------------------------------------------
// Flash attention — fp16 in gmem: cp.async K/V (no converter side-channel),
// u32 Q fragment loads, f16 ctx output. Math identical to R9 (fp32 softmax).
// ---------------------------------------------------------------------------
#define SK    64                      // keys per s-tile
#define KSTRH 72                      // halves per K/V smem row (144 B)
#define KVTB  (SK * KSTRH * 2)        // 9216 B per tile
#define OFF_VH (2 * KVTB)
#define OFF_PH (4 * KVTB)
#define FA_SMEM_BYTES (4 * KVTB + 128 * KSTRH * 2)  // 55296

__global__ __launch_bounds__(256, 2)
void flash_attn_f16(const __half* __restrict__ Q, const __half* __restrict__ K,
                    const __half* __restrict__ V, const int* __restrict__ mask,
                    __half* __restrict__ ctx)
{
    extern __shared__ char smc[];
    const uint32_t sb = smem_to_u32(smc);

    const int tid  = threadIdx.x;
    const int wid  = tid >> 5;
    const int lane = tid & 31;
    const int g    = lane >> 2;
    const int tg   = lane & 3;
    const int t0 = blockIdx.x * 128;
    const int h  = blockIdx.y;
    const int n  = blockIdx.z;

    // ---- Q fragments: direct u32 loads from f16 gmem ----
    const size_t qrow = (size_t)(n * T_S + t0 + wid * 16 + g);
    const __half* Qp0 = Q + qrow * D_M + h * DH;
    const __half* Qp1 = Qp0 + (size_t)8 * D_M;
    uint32_t qf[4][4];
    #pragma unroll
    for (int ks = 0; ks < 4; ++ks) {
        const int c = ks * 16 + 2 * tg;
        qf[ks][0] = *(const uint32_t*)(Qp0 + c);
        qf[ks][1] = *(const uint32_t*)(Qp1 + c);
        qf[ks][2] = *(const uint32_t*)(Qp0 + c + 8);
        qf[ks][3] = *(const uint32_t*)(Qp1 + c + 8);
    }

    const float rsc0 = (mask[n * T_S + t0 + wid * 16 + g]     != 0) ? 0.125f : 0.0f;
    const float rsc1 = (mask[n * T_S + t0 + wid * 16 + g + 8] != 0) ? 0.125f : 0.0f;

    float m0 = -1e30f, l0 = 0.0f, m1 = -1e30f, l1 = 0.0f;
    float oacc[8][4];
    #pragma unroll
    for (int nt = 0; nt < 8; ++nt)
        #pragma unroll
        for (int u = 0; u < 4; ++u) oacc[nt][u] = 0.0f;

    // ---- cp.async mapping: thread -> (key row tid>>2, 16-half quarter) ----
    const int cr = tid >> 2;              // 0..63
    const int cq = (tid & 3) * 16;        // halves: 0,16,32,48
    const __half* Kg = K + ((size_t)(n * T_S) + cr) * D_M + h * DH + cq;
    const __half* Vg = V + ((size_t)(n * T_S) + cr) * D_M + h * DH + cq;
    const uint32_t cdst = (uint32_t)(cr * (KSTRH * 2) + cq * 2);  // bytes

    // ---- ldmatrix per-lane offsets (bytes) ----
    const uint32_t koff = (uint32_t)(((lane & 7) * KSTRH + ((lane >> 3) & 1) * 8) * 2);
    const uint32_t voff = (uint32_t)((lane & 15) * KSTRH * 2);
    const uint32_t poff = (uint32_t)((lane & 15) * KSTRH * 2 + ((lane >> 4) & 1) * 16);
    const uint32_t PhB  = sb + OFF_PH + wid * 16 * (KSTRH * 2);

    // prologue: s-tile 0 -> buf 0
    cpa16(sb + cdst,                 Kg);
    cpa16(sb + cdst + 16,            Kg + 8);
    cpa16(sb + OFF_VH + cdst,        Vg);
    cpa16(sb + OFF_VH + cdst + 16,   Vg + 8);
    CP_COMMIT();

    const int NST = T_S / SK;   // 32
    for (int st = 0; st < NST; ++st) {
        const int buf = st & 1;
        asm volatile("cp.async.wait_group 0;" ::: "memory");
        __syncthreads();

        if (st + 1 < NST) {
            const int nb = buf ^ 1;
            const size_t go = (size_t)(st + 1) * SK * D_M;
            cpa16(sb + nb * KVTB + cdst,               Kg + go);
            cpa16(sb + nb * KVTB + cdst + 16,          Kg + go + 8);
            cpa16(sb + OFF_VH + nb * KVTB + cdst,      Vg + go);
            cpa16(sb + OFF_VH + nb * KVTB + cdst + 16, Vg + go + 8);
            CP_COMMIT();
        }

        const uint32_t KhB = sb + buf * KVTB;
        const uint32_t VhB = sb + OFF_VH + buf * KVTB;

        // ---- S = Q K^T : 4 k16-steps x 8 n-tiles ----
        float sacc[8][4];
        #pragma unroll
        for (int nt = 0; nt < 8; ++nt)
            #pragma unroll
            for (int u = 0; u < 4; ++u) sacc[nt][u] = 0.0f;

        #pragma unroll
        for (int ks = 0; ks < 4; ++ks) {
            #pragma unroll
            for (int nt = 0; nt < 8; ++nt) {
                uint32_t b0, b1;
                ldsm_x2(KhB + (uint32_t)((nt * 8 * KSTRH + ks * 16) * 2) + koff, b0, b1);
                mma_f16(sacc[nt], qf[ks], b0, b1);
            }
        }

        // ---- online softmax (rows g, g+8; reduce over tg lanes) ----
        {
            float mx0 = -1e30f, mx1 = -1e30f;
            #pragma unroll
            for (int nt = 0; nt < 8; ++nt) {
                sacc[nt][0] *= rsc0; sacc[nt][1] *= rsc0;
                sacc[nt][2] *= rsc1; sacc[nt][3] *= rsc1;
                mx0 = fmaxf(mx0, fmaxf(sacc[nt][0], sacc[nt][1]));
                mx1 = fmaxf(mx1, fmaxf(sacc[nt][2], sacc[nt][3]));
            }
            mx0 = fmaxf(mx0, __shfl_xor_sync(0xffffffffu, mx0, 1));
            mx0 = fmaxf(mx0, __shfl_xor_sync(0xffffffffu, mx0, 2));
            mx1 = fmaxf(mx1, __shfl_xor_sync(0xffffffffu, mx1, 1));
            mx1 = fmaxf(mx1, __shfl_xor_sync(0xffffffffu, mx1, 2));

            const float mn0 = fmaxf(m0, mx0), mn1 = fmaxf(m1, mx1);
            const float cf0 = __expf(m0 - mn0), cf1 = __expf(m1 - mn1);
            float rs0 = 0.0f, rs1 = 0.0f;

            char* Pr0 = smc + OFF_PH + (wid * 16 + g)     * (KSTRH * 2) + tg * 4;
            char* Pr1 = smc + OFF_PH + (wid * 16 + g + 8) * (KSTRH * 2) + tg * 4;
            #pragma unroll
            for (int nt = 0; nt < 8; ++nt) {
                float p0 = __expf(sacc[nt][0] - mn0);
                float p1 = __expf(sacc[nt][1] - mn0);
                float p2 = __expf(sacc[nt][2] - mn1);
                float p3 = __expf(sacc[nt][3] - mn1);
                rs0 += p0 + p1;
                rs1 += p2 + p3;
                *(uint32_t*)(Pr0 + nt * 16) = packh2(p0, p1);
                *(uint32_t*)(Pr1 + nt * 16) = packh2(p2, p3);
            }
            rs0 += __shfl_xor_sync(0xffffffffu, rs0, 1);
            rs0 += __shfl_xor_sync(0xffffffffu, rs0, 2);
            rs1 += __shfl_xor_sync(0xffffffffu, rs1, 1);
            rs1 += __shfl_xor_sync(0xffffffffu, rs1, 2);

            m0 = mn0; l0 = l0 * cf0 + rs0;
            m1 = mn1; l1 = l1 * cf1 + rs1;
            #pragma unroll
            for (int nt = 0; nt < 8; ++nt) {
                oacc[nt][0] *= cf0; oacc[nt][1] *= cf0;
                oacc[nt][2] *= cf1; oacc[nt][3] *= cf1;
            }
        }
        __syncwarp();

        // ---- O += P V : 4 k16-steps (keys) x 8 n-tiles (dh) ----
        #pragma unroll
        for (int ks = 0; ks < 4; ++ks) {
            uint32_t af[4];
            ldsm_x4(PhB + ks * 32 + poff, af);
            #pragma unroll
            for (int nt = 0; nt < 8; ++nt) {
                uint32_t b0, b1;
                ldsm_x2t(VhB + (uint32_t)((ks * 16 * KSTRH + nt * 8) * 2) + voff, b0, b1);
                mma_f16(oacc[nt], af, b0, b1);
            }
        }
    }

    // ---- epilogue: normalize, write ctx as f16 ----
    const float inv0 = 1.0f / l0, inv1 = 1.0f / l1;
    __half* op0 = ctx + qrow * D_M + h * DH;
    __half* op1 = op0 + (size_t)8 * D_M;
    #pragma unroll
    for (int nt = 0; nt < 8; ++nt) {
        const int col = nt * 8 + tg * 2;
        *(uint32_t*)(op0 + col) = packh2(oacc[nt][0] * inv0, oacc[nt][1] * inv0);
        *(uint32_t*)(op1 + col) = packh2(oacc[nt][2] * inv1, oacc[nt][3] * inv1);
    }
}

// ---------------------------------------------------------------------------
// Launch
// ---------------------------------------------------------------------------
extern "C" void kernel_launch(void* const* d_in, const int* in_sizes, int n_in,
                              void* d_out, int out_size)
{
    (void)in_sizes; (void)n_in; (void)out_size;

    const float* query = (const float*)d_in[0];
    const int*   mask  = (const int*)  d_in[1];
    const float* Wq    = (const float*)d_in[2];
    const float* bq    = (const float*)d_in[3];
    const float* Wk    = (const float*)d_in[4];
    const float* bk    = (const float*)d_in[5];
    const float* Wv    = (const float*)d_in[6];
    const float* bv    = (const float*)d_in[7];
    const float* Wo    = (const float*)d_in[8];
    const float* bo    = (const float*)d_in[9];
    float* out = (float*)d_out;

    __half *qh, *Qh, *Kh, *Vh, *ctxh, *Wqh, *Wkh, *Wvh, *Woh;
    cudaGetSymbolAddress((void**)&qh,   g_qh);
    cudaGetSymbolAddress((void**)&Qh,   g_Qh);
    cudaGetSymbolAddress((void**)&Kh,   g_Kh);
    cudaGetSymbolAddress((void**)&Vh,   g_Vh);
    cudaGetSymbolAddress((void**)&ctxh, g_ctxh);
    cudaGetSymbolAddress((void**)&Wqh,  g_Wqh);
    cudaGetSymbolAddress((void**)&Wkh,  g_Wkh);
    cudaGetSymbolAddress((void**)&Wvh,  g_Wvh);
    cudaGetSymbolAddress((void**)&Woh,  g_Woh);

    cudaFuncSetAttribute(hgemm_f16<__half>,
                         cudaFuncAttributeMaxDynamicSharedMemorySize,
                         GEMM_SMEM_BYTES);
    cudaFuncSetAttribute(hgemm_f16<float>,
                         cudaFuncAttributeMaxDynamicSharedMemorySize,
                         GEMM_SMEM_BYTES);
    cudaFuncSetAttribute(flash_attn_f16,
                         cudaFuncAttributeMaxDynamicSharedMemorySize,
                         FA_SMEM_BYTES);

    // fp32 -> fp16 converts (query + 4 weights)
    const int nQ = MROWS * D_M;          // 8388608
    const int nW = D_M * D_M;            // 1048576
    cvt_f32_f16<<<nQ / 8 / 256, 256>>>(query, qh, nQ);
    cvt_f32_f16<<<nW / 8 / 256, 256>>>(Wq, Wqh, nW);
    cvt_f32_f16<<<nW / 8 / 256, 256>>>(Wk, Wkh, nW);
    cvt_f32_f16<<<nW / 8 / 256, 256>>>(Wv, Wvh, nW);
    cvt_f32_f16<<<nW / 8 / 256, 256>>>(Wo, Woh, nW);

    dim3 gemm_grid(D_M / 128, MROWS / 128);  // (8, 64)

    hgemm_f16<__half><<<gemm_grid, 256, GEMM_SMEM_BYTES>>>(qh, Wqh, bq, Qh);
    hgemm_f16<__half><<<gemm_grid, 256, GEMM_SMEM_BYTES>>>(qh, Wkh, bk, Kh);
    hgemm_f16<__half><<<gemm_grid, 256, GEMM_SMEM_BYTES>>>(qh, Wvh, bv, Vh);

    flash_attn_f16<<<dim3(T_S / 128, H_N, N_B), 256, FA_SMEM_BYTES>>>(
        Qh, Kh, Vh, mask, ctxh);

    hgemm_f16<float><<<gemm_grid, 256, GEMM_SMEM_BYTES>>>(ctxh, Woh, bo, out);
}

// round 12
// speedup vs baseline: 1.9604x; 1.0618x over previous
#include <cuda_runtime.h>
#include <cuda_fp16.h>
#include <math.h>
#include <stdint.h>

// Problem constants
#define N_B   4
#define T_S   2048
#define D_M   1024
#define H_N   16
#define DH    64
#define MROWS (N_B * T_S)   // 8192
#define GK    1024          // GEMM K

// ---------------------------------------------------------------------------
// Scratch (alloc-free rule: __device__ globals) — all f16
// ---------------------------------------------------------------------------
__device__ __half g_qh  [(size_t)MROWS * D_M];
__device__ __half g_Qh  [(size_t)MROWS * D_M];
__device__ __half g_Kh  [(size_t)MROWS * D_M];
__device__ __half g_Vh  [(size_t)MROWS * D_M];
__device__ __half g_ctxh[(size_t)MROWS * D_M];
__device__ __half g_Wqh [(size_t)D_M * D_M];
__device__ __half g_Wkh [(size_t)D_M * D_M];
__device__ __half g_Wvh [(size_t)D_M * D_M];
__device__ __half g_Woh [(size_t)D_M * D_M];

// ---------------------------------------------------------------------------
// Helpers (sm_100 plain target: NO tcgen05)
// ---------------------------------------------------------------------------
__device__ __forceinline__ uint32_t smem_to_u32(const void* p) {
    uint32_t a;
    asm("{ .reg .u64 t; cvta.to.shared.u64 t, %1; cvt.u32.u64 %0, t; }"
        : "=r"(a) : "l"(p));
    return a;
}
__device__ __forceinline__ void cpa16(uint32_t dst, const void* src) {
    asm volatile("cp.async.cg.shared.global [%0], [%1], 16;"
                 :: "r"(dst), "l"(src) : "memory");
}
#define CP_COMMIT() asm volatile("cp.async.commit_group;" ::: "memory")

__device__ __forceinline__ uint32_t packh2(float lo, float hi) {
    __half2 h = __floats2half2_rn(lo, hi);
    return *(uint32_t*)&h;
}
// D(16x8,f32) += A(16x16,f16 row) * B(16x8,f16 col)
__device__ __forceinline__ void mma_f16(float* d, const uint32_t* a,
                                        uint32_t b0, uint32_t b1) {
    asm volatile(
        "mma.sync.aligned.m16n8k16.row.col.f32.f16.f16.f32 "
        "{%0,%1,%2,%3}, {%4,%5,%6,%7}, {%8,%9}, {%0,%1,%2,%3};"
        : "+f"(d[0]), "+f"(d[1]), "+f"(d[2]), "+f"(d[3])
        : "r"(a[0]), "r"(a[1]), "r"(a[2]), "r"(a[3]),
          "r"(b0), "r"(b1));
}
__device__ __forceinline__ void ldsm_x2(uint32_t addr, uint32_t& r0, uint32_t& r1) {
    asm volatile("ldmatrix.sync.aligned.m8n8.x2.shared.b16 {%0,%1}, [%2];"
                 : "=r"(r0), "=r"(r1) : "r"(addr));
}
__device__ __forceinline__ void ldsm_x2t(uint32_t addr, uint32_t& r0, uint32_t& r1) {
    asm volatile("ldmatrix.sync.aligned.m8n8.x2.trans.shared.b16 {%0,%1}, [%2];"
                 : "=r"(r0), "=r"(r1) : "r"(addr));
}
__device__ __forceinline__ void ldsm_x4(uint32_t addr, uint32_t* r) {
    asm volatile("ldmatrix.sync.aligned.m8n8.x4.shared.b16 {%0,%1,%2,%3}, [%4];"
                 : "=r"(r[0]), "=r"(r[1]), "=r"(r[2]), "=r"(r[3]) : "r"(addr));
}

// ---------------------------------------------------------------------------
// fp32 -> fp16 bulk convert
// ---------------------------------------------------------------------------
__global__ void cvt_f32_f16(const float* __restrict__ in,
                            __half* __restrict__ out, int n)
{
    int i = (blockIdx.x * blockDim.x + threadIdx.x) * 8;
    if (i >= n) return;
    float4 a = *(const float4*)(in + i);
    float4 b = *(const float4*)(in + i + 4);
    uint4 o;
    o.x = packh2(a.x, a.y); o.y = packh2(a.z, a.w);
    o.z = packh2(b.x, b.y); o.w = packh2(b.z, b.w);
    *(uint4*)(out + i) = o;
}

// ---------------------------------------------------------------------------
// Pure FP16 GEMM, 3-stage cp.async pipeline, ONE barrier per k-tile.
// C[m][n] = sum_k A[m][k]*B[n][k] + bias[n]; 128x128x32 tile, 8 warps (2Mx4N).
// ---------------------------------------------------------------------------
#define GSTR   40                       // halves per smem row (80 B)
#define GTILEB (128 * GSTR * 2)         // 10240 B per tile
#define GEMM_SMEM_BYTES (6 * GTILEB)    // 3 stages x (A,B) = 61440 B

template<typename OutT>
__global__ __launch_bounds__(256, 2)
void hgemm_f16(const __half* __restrict__ A, const __half* __restrict__ B,
               const float* __restrict__ bias, OutT* __restrict__ C)
{
    extern __shared__ char smc[];
    const uint32_t sb = smem_to_u32(smc);
    const int tid  = threadIdx.x;
    const int wid  = tid >> 5;
    const int lane = tid & 31;
    const int g    = lane >> 2;
    const int tg   = lane & 3;
    const int warp_m = wid & 1;
    const int warp_n = wid >> 1;
    const int m0 = blockIdx.y * 128;
    const int n0 = blockIdx.x * 128;

    const int lr = tid >> 1;
    const int lc = (tid & 1) * 16;
    const __half* Ag = A + (size_t)(m0 + lr) * GK + lc;
    const __half* Bg = B + (size_t)(n0 + lr) * GK + lc;
    const uint32_t sdst = (uint32_t)(lr * (GSTR * 2) + lc * 2);

    const uint32_t aoff = (uint32_t)(((lane & 15) * GSTR + (lane >> 4) * 8) * 2);
    const uint32_t boff = (uint32_t)(((lane & 7) * GSTR + ((lane >> 3) & 1) * 8) * 2);

    // prologue: tiles 0 and 1 into slots 0,1 (separate commit groups)
    #pragma unroll
    for (int p = 0; p < 2; ++p) {
        cpa16(sb + p * GTILEB + sdst,                Ag + p * 32);
        cpa16(sb + p * GTILEB + sdst + 16,           Ag + p * 32 + 8);
        cpa16(sb + (3 + p) * GTILEB + sdst,          Bg + p * 32);
        cpa16(sb + (3 + p) * GTILEB + sdst + 16,     Bg + p * 32 + 8);
        CP_COMMIT();
    }

    float acc[4][4][4];
    #pragma unroll
    for (int mt = 0; mt < 4; ++mt)
        #pragma unroll
        for (int nt = 0; nt < 4; ++nt)
            #pragma unroll
            for (int u = 0; u < 4; ++u) acc[mt][nt][u] = 0.0f;

    const int NT = GK / 32;   // 32 k-tiles
    int slot = 0, wslot = 2;  // compute slot, next write slot
    for (int kt = 0; kt < NT; ++kt) {
        if (kt + 1 < NT) {
            asm volatile("cp.async.wait_group 1;" ::: "memory");
        } else {
            asm volatile("cp.async.wait_group 0;" ::: "memory");
        }
        __syncthreads();   // tile kt visible; also: all warps done reading the
                           // slot about to be overwritten (read at iter kt-1)

        if (kt + 2 < NT) {
            const __half* Ag2 = Ag + (kt + 2) * 32;
            const __half* Bg2 = Bg + (kt + 2) * 32;
            cpa16(sb + wslot * GTILEB + sdst,            Ag2);
            cpa16(sb + wslot * GTILEB + sdst + 16,       Ag2 + 8);
            cpa16(sb + (3 + wslot) * GTILEB + sdst,      Bg2);
            cpa16(sb + (3 + wslot) * GTILEB + sdst + 16, Bg2 + 8);
            CP_COMMIT();
            if (++wslot == 3) wslot = 0;
        }

        const uint32_t AB = sb + slot * GTILEB;
        const uint32_t BB = sb + (3 + slot) * GTILEB;
        if (++slot == 3) slot = 0;

        #pragma unroll
        for (int ks = 0; ks < 2; ++ks) {
            uint32_t af[4][4], bf[4][2];
            #pragma unroll
            for (int mt = 0; mt < 4; ++mt)
                ldsm_x4(AB + (uint32_t)((warp_m * 64 + mt * 16) * GSTR * 2 + ks * 32)
                           + aoff, af[mt]);
            #pragma unroll
            for (int nt = 0; nt < 4; ++nt)
                ldsm_x2(BB + (uint32_t)((warp_n * 32 + nt * 8) * GSTR * 2 + ks * 32)
                           + boff, bf[nt][0], bf[nt][1]);
            #pragma unroll
            for (int mt = 0; mt < 4; ++mt)
                #pragma unroll
                for (int nt = 0; nt < 4; ++nt)
                    mma_f16(acc[mt][nt], af[mt], bf[nt][0], bf[nt][1]);
        }
    }

    #pragma unroll
    for (int nt = 0; nt < 4; ++nt) {
        const int col = n0 + warp_n * 32 + nt * 8 + tg * 2;
        const float b0 = bias[col], b1 = bias[col + 1];
        #pragma unroll
        for (int mt = 0; mt < 4; ++mt) {
            const int row = m0 + warp_m * 64 + mt * 16 + g;
            if (sizeof(OutT) == 2) {
                __half* Ch = (__half*)C;
                *(uint32_t*)(Ch + (size_t)row * D_M + col) =
                    packh2(acc[mt][nt][0] + b0, acc[mt][nt][1] + b1);
                *(uint32_t*)(Ch + (size_t)(row + 8) * D_M + col) =
                    packh2(acc[mt][nt][2] + b0, acc[mt][nt][3] + b1);
            } else {
                float* Cf = (float*)C;
                *(float2*)(Cf + (size_t)row * D_M + col) =
                    make_float2(acc[mt][nt][0] + b0, acc[mt][nt][1] + b1);
                *(float2*)(Cf + (size_t)(row + 8) * D_M + col) =
                    make_float2(acc[mt][nt][2] + b0, acc[mt][nt][3] + b1);
            }
        }
    }
}

// ---------------------------------------------------------------------------
// Flash attention — R12: P kept IN REGISTERS (C-fragment of S == A-fragment
// of PV for m16n8k16; FA-2 trick). No P smem, no ldsm_x4, no __syncwarp.
// Same packh2 rounding point => bit-identical numerics to R11.
// ---------------------------------------------------------------------------
#define SK    64
#define KSTRH 72                      // halves per K/V smem row (144 B)
#define KVTB  (SK * KSTRH * 2)        // 9216 B per tile
#define OFF_VH (2 * KVTB)
#define FA_SMEM_BYTES (4 * KVTB)      // 36864 B

__global__ __launch_bounds__(256, 2)
void flash_attn_f16(const __half* __restrict__ Q, const __half* __restrict__ K,
                    const __half* __restrict__ V, const int* __restrict__ mask,
                    __half* __restrict__ ctx)
{
    extern __shared__ char smc[];
    const uint32_t sb = smem_to_u32(smc);

    const int tid  = threadIdx.x;
    const int wid  = tid >> 5;
    const int lane = tid & 31;
    const int g    = lane >> 2;
    const int tg   = lane & 3;
    const int t0 = blockIdx.x * 128;
    const int h  = blockIdx.y;
    const int n  = blockIdx.z;

    const size_t qrow = (size_t)(n * T_S + t0 + wid * 16 + g);
    const __half* Qp0 = Q + qrow * D_M + h * DH;
    const __half* Qp1 = Qp0 + (size_t)8 * D_M;
    uint32_t qf[4][4];
    #pragma unroll
    for (int ks = 0; ks < 4; ++ks) {
        const int c = ks * 16 + 2 * tg;
        qf[ks][0] = *(const uint32_t*)(Qp0 + c);
        qf[ks][1] = *(const uint32_t*)(Qp1 + c);
        qf[ks][2] = *(const uint32_t*)(Qp0 + c + 8);
        qf[ks][3] = *(const uint32_t*)(Qp1 + c + 8);
    }

    const float rsc0 = (mask[n * T_S + t0 + wid * 16 + g]     != 0) ? 0.125f : 0.0f;
    const float rsc1 = (mask[n * T_S + t0 + wid * 16 + g + 8] != 0) ? 0.125f : 0.0f;

    float m0 = -1e30f, l0 = 0.0f, m1 = -1e30f, l1 = 0.0f;
    float oacc[8][4];
    #pragma unroll
    for (int nt = 0; nt < 8; ++nt)
        #pragma unroll
        for (int u = 0; u < 4; ++u) oacc[nt][u] = 0.0f;

    const int cr = tid >> 2;
    const int cq = (tid & 3) * 16;
    const __half* Kg = K + ((size_t)(n * T_S) + cr) * D_M + h * DH + cq;
    const __half* Vg = V + ((size_t)(n * T_S) + cr) * D_M + h * DH + cq;
    const uint32_t cdst = (uint32_t)(cr * (KSTRH * 2) + cq * 2);

    const uint32_t koff = (uint32_t)(((lane & 7) * KSTRH + ((lane >> 3) & 1) * 8) * 2);
    const uint32_t voff = (uint32_t)((lane & 15) * KSTRH * 2);

    cpa16(sb + cdst,               Kg);
    cpa16(sb + cdst + 16,          Kg + 8);
    cpa16(sb + OFF_VH + cdst,      Vg);
    cpa16(sb + OFF_VH + cdst + 16, Vg + 8);
    CP_COMMIT();

    const int NST = T_S / SK;   // 32
    for (int st = 0; st < NST; ++st) {
        const int buf = st & 1;
        asm volatile("cp.async.wait_group 0;" ::: "memory");
        __syncthreads();

        if (st + 1 < NST) {
            const int nb = buf ^ 1;
            const size_t go = (size_t)(st + 1) * SK * D_M;
            cpa16(sb + nb * KVTB + cdst,               Kg + go);
            cpa16(sb + nb * KVTB + cdst + 16,          Kg + go + 8);
            cpa16(sb + OFF_VH + nb * KVTB + cdst,      Vg + go);
            cpa16(sb + OFF_VH + nb * KVTB + cdst + 16, Vg + go + 8);
            CP_COMMIT();
        }

        const uint32_t KhB = sb + buf * KVTB;
        const uint32_t VhB = sb + OFF_VH + buf * KVTB;

        // ---- S = Q K^T ----
        float sacc[8][4];
        #pragma unroll
        for (int nt = 0; nt < 8; ++nt)
            #pragma unroll
            for (int u = 0; u < 4; ++u) sacc[nt][u] = 0.0f;

        #pragma unroll
        for (int ks = 0; ks < 4; ++ks) {
            #pragma unroll
            for (int nt = 0; nt < 8; ++nt) {
                uint32_t b0, b1;
                ldsm_x2(KhB + (uint32_t)((nt * 8 * KSTRH + ks * 16) * 2) + koff, b0, b1);
                mma_f16(sacc[nt], qf[ks], b0, b1);
            }
        }

        // ---- online softmax -> P packed in registers (A-fragment layout) ----
        uint32_t pf[8][2];
        {
            float mx0 = -1e30f, mx1 = -1e30f;
            #pragma unroll
            for (int nt = 0; nt < 8; ++nt) {
                sacc[nt][0] *= rsc0; sacc[nt][1] *= rsc0;
                sacc[nt][2] *= rsc1; sacc[nt][3] *= rsc1;
                mx0 = fmaxf(mx0, fmaxf(sacc[nt][0], sacc[nt][1]));
                mx1 = fmaxf(mx1, fmaxf(sacc[nt][2], sacc[nt][3]));
            }
            mx0 = fmaxf(mx0, __shfl_xor_sync(0xffffffffu, mx0, 1));
            mx0 = fmaxf(mx0, __shfl_xor_sync(0xffffffffu, mx0, 2));
            mx1 = fmaxf(mx1, __shfl_xor_sync(0xffffffffu, mx1, 1));
            mx1 = fmaxf(mx1, __shfl_xor_sync(0xffffffffu, mx1, 2));

            const float mn0 = fmaxf(m0, mx0), mn1 = fmaxf(m1, mx1);
            const float cf0 = __expf(m0 - mn0), cf1 = __expf(m1 - mn1);
            float rs0 = 0.0f, rs1 = 0.0f;

            #pragma unroll
            for (int nt = 0; nt < 8; ++nt) {
                float p0 = __expf(sacc[nt][0] - mn0);
                float p1 = __expf(sacc[nt][1] - mn0);
                float p2 = __expf(sacc[nt][2] - mn1);
                float p3 = __expf(sacc[nt][3] - mn1);
                rs0 += p0 + p1;
                rs1 += p2 + p3;
                pf[nt][0] = packh2(p0, p1);   // row g,   keys 2tg..2tg+1
                pf[nt][1] = packh2(p2, p3);   // row g+8, keys 2tg..2tg+1
            }
            rs0 += __shfl_xor_sync(0xffffffffu, rs0, 1);
            rs0 += __shfl_xor_sync(0xffffffffu, rs0, 2);
            rs1 += __shfl_xor_sync(0xffffffffu, rs1, 1);
            rs1 += __shfl_xor_sync(0xffffffffu, rs1, 2);

            m0 = mn0; l0 = l0 * cf0 + rs0;
            m1 = mn1; l1 = l1 * cf1 + rs1;
            #pragma unroll
            for (int nt = 0; nt < 8; ++nt) {
                oacc[nt][0] *= cf0; oacc[nt][1] *= cf0;
                oacc[nt][2] *= cf1; oacc[nt][3] *= cf1;
            }
        }

        // ---- O += P V : A-fragments straight from pf registers ----
        #pragma unroll
        for (int ks = 0; ks < 4; ++ks) {
            uint32_t af[4];
            af[0] = pf[2 * ks][0];       // row g,   keys 16ks+2tg..+1
            af[1] = pf[2 * ks][1];       // row g+8
            af[2] = pf[2 * ks + 1][0];   // row g,   keys 16ks+8+2tg..+1
            af[3] = pf[2 * ks + 1][1];   // row g+8
            #pragma unroll
            for (int nt = 0; nt < 8; ++nt) {
                uint32_t b0, b1;
                ldsm_x2t(VhB + (uint32_t)((ks * 16 * KSTRH + nt * 8) * 2) + voff, b0, b1);
                mma_f16(oacc[nt], af, b0, b1);
            }
        }
    }

    const float inv0 = 1.0f / l0, inv1 = 1.0f / l1;
    __half* op0 = ctx + qrow * D_M + h * DH;
    __half* op1 = op0 + (size_t)8 * D_M;
    #pragma unroll
    for (int nt = 0; nt < 8; ++nt) {
        const int col = nt * 8 + tg * 2;
        *(uint32_t*)(op0 + col) = packh2(oacc[nt][0] * inv0, oacc[nt][1] * inv0);
        *(uint32_t*)(op1 + col) = packh2(oacc[nt][2] * inv1, oacc[nt][3] * inv1);
    }
}

// ---------------------------------------------------------------------------
// Launch
// ---------------------------------------------------------------------------
extern "C" void kernel_launch(void* const* d_in, const int* in_sizes, int n_in,
                              void* d_out, int out_size)
{
    (void)in_sizes; (void)n_in; (void)out_size;

    const float* query = (const float*)d_in[0];
    const int*   mask  = (const int*)  d_in[1];
    const float* Wq    = (const float*)d_in[2];
    const float* bq    = (const float*)d_in[3];
    const float* Wk    = (const float*)d_in[4];
    const float* bk    = (const float*)d_in[5];
    const float* Wv    = (const float*)d_in[6];
    const float* bv    = (const float*)d_in[7];
    const float* Wo    = (const float*)d_in[8];
    const float* bo    = (const float*)d_in[9];
    float* out = (float*)d_out;

    __half *qh, *Qh, *Kh, *Vh, *ctxh, *Wqh, *Wkh, *Wvh, *Woh;
    cudaGetSymbolAddress((void**)&qh,   g_qh);
    cudaGetSymbolAddress((void**)&Qh,   g_Qh);
    cudaGetSymbolAddress((void**)&Kh,   g_Kh);
    cudaGetSymbolAddress((void**)&Vh,   g_Vh);
    cudaGetSymbolAddress((void**)&ctxh, g_ctxh);
    cudaGetSymbolAddress((void**)&Wqh,  g_Wqh);
    cudaGetSymbolAddress((void**)&Wkh,  g_Wkh);
    cudaGetSymbolAddress((void**)&Wvh,  g_Wvh);
    cudaGetSymbolAddress((void**)&Woh,  g_Woh);

    cudaFuncSetAttribute(hgemm_f16<__half>,
                         cudaFuncAttributeMaxDynamicSharedMemorySize,
                         GEMM_SMEM_BYTES);
    cudaFuncSetAttribute(hgemm_f16<float>,
                         cudaFuncAttributeMaxDynamicSharedMemorySize,
                         GEMM_SMEM_BYTES);
    cudaFuncSetAttribute(flash_attn_f16,
                         cudaFuncAttributeMaxDynamicSharedMemorySize,
                         FA_SMEM_BYTES);

    const int nQ = MROWS * D_M;
    const int nW = D_M * D_M;
    cvt_f32_f16<<<nQ / 8 / 256, 256>>>(query, qh, nQ);
    cvt_f32_f16<<<nW / 8 / 256, 256>>>(Wq, Wqh, nW);
    cvt_f32_f16<<<nW / 8 / 256, 256>>>(Wk, Wkh, nW);
    cvt_f32_f16<<<nW / 8 / 256, 256>>>(Wv, Wvh, nW);
    cvt_f32_f16<<<nW / 8 / 256, 256>>>(Wo, Woh, nW);

    dim3 gemm_grid(D_M / 128, MROWS / 128);  // (8, 64)

    hgemm_f16<__half><<<gemm_grid, 256, GEMM_SMEM_BYTES>>>(qh, Wqh, bq, Qh);
    hgemm_f16<__half><<<gemm_grid, 256, GEMM_SMEM_BYTES>>>(qh, Wkh, bk, Kh);
    hgemm_f16<__half><<<gemm_grid, 256, GEMM_SMEM_BYTES>>>(qh, Wvh, bv, Vh);

    flash_attn_f16<<<dim3(T_S / 128, H_N, N_B), 256, FA_SMEM_BYTES>>>(
        Qh, Kh, Vh, mask, ctxh);

    hgemm_f16<float><<<gemm_grid, 256, GEMM_SMEM_BYTES>>>(ctxh, Woh, bo, out);
}